// round 14
// baseline (speedup 1.0000x reference)
#include <cuda_runtime.h>
#include <cuda_fp16.h>
#include <mma.h>
#include <math.h>
#include <float.h>

using namespace nvcuda;

// ---------------------------------------------------------------------------
// GAT 2-layer.  Softmax-aggregate raw x (pre-GEMM), apply W1 after as dense
// tensor-core GEMM (fragments straight from global; no block barriers in the
// head loop); h1 never materialized.
// ---------------------------------------------------------------------------

#define MAXN 50048
#define MAXE 800000
#define MAXT (MAXE + MAXN)
#define SCANB 1024

__device__ __half g_xh[(size_t)MAXN * 64];    // x in fp16 (gather source)
__device__ __half g_xa[(size_t)MAXN * 512];   // normalized aggregated x, per head
__device__ __half g_w1h[64 * 512];            // W1 fp16
__device__ __half g_wext[64 * 16];            // W1 @ att (a_src 0-7, a_dst 8-15)
__device__ float g_as1[MAXN * 8];
__device__ float g_ad1[MAXN * 8];
__device__ int   g_deg[MAXN];
__device__ int   g_rowptr[MAXN];
__device__ int   g_cursor[MAXN];
__device__ int   g_csr[MAXT];
__device__ float g_h2v[MAXN];
__device__ unsigned g_gms[8];
__device__ unsigned g_g2[2];
__device__ int   g_total;
__device__ int   g_is64;

__device__ __forceinline__ unsigned f_enc(float f) {
    unsigned u = __float_as_uint(f);
    return (u & 0x80000000u) ? ~u : (u | 0x80000000u);
}
__device__ __forceinline__ float f_dec(unsigned e) {
    return __uint_as_float((e & 0x80000000u) ? (e & 0x7fffffffu) : ~e);
}

// ---------------------------------------------------------------------------
__global__ void k_pre(const float* __restrict__ W,
                      const float* __restrict__ att_s,
                      const float* __restrict__ att_d,
                      const unsigned int* __restrict__ edges, int E, int N) {
    int g = blockIdx.x * blockDim.x + threadIdx.x;
    int stride = gridDim.x * blockDim.x;
    for (int i = g; i < N; i += stride) g_deg[i] = 1;   // self-loop
    for (int i = g * 4; i < 64 * 512; i += stride * 4) {
        float4 v = *(const float4*)&W[i];
        __half2 p0 = __floats2half2_rn(v.x, v.y);
        __half2 p1 = __floats2half2_rn(v.z, v.w);
        *(uint2*)&g_w1h[i] = make_uint2(*(unsigned*)&p0, *(unsigned*)&p1);
    }
    for (int idx = g; idx < 64 * 16; idx += stride) {
        int k = idx >> 4, j = idx & 15;
        int head = j & 7;
        const float* att = (j < 8) ? att_s : att_d;
        float s = 0.f;
        const float* wr = &W[(size_t)k * 512 + head * 64];
        const float* ar = &att[head * 64];
        #pragma unroll 8
        for (int c = 0; c < 64; c++) s += wr[c] * ar[c];
        g_wext[k * 16 + j] = __float2half_rn(s);
    }
    if (g < 8) g_gms[g] = 0u;
    if (g < 2) g_g2[g] = 0u;
    if (g == 0) {
        g_total = 0;
        int n = E < 64 ? E : 64;
        int all0 = 1;
        for (int j = 0; j < n; j++)
            if (edges[2 * j + 1] != 0u) all0 = 0;
        g_is64 = all0;
    }
}

__global__ void k_deg(const int* __restrict__ edges, int E) {
    int e = blockIdx.x * blockDim.x + threadIdx.x;
    if (e >= E) return;
    int d = g_is64 ? (int)((const long long*)edges)[(size_t)E + e]
                   : edges[E + e];
    atomicAdd(&g_deg[d], 1);
}

// Single-kernel CSR build: block-local scan + atomic base allocation.
__global__ __launch_bounds__(SCANB) void k_build(int N) {
    __shared__ int wsum[32];
    __shared__ int base;
    int t = threadIdx.x, idx = blockIdx.x * SCANB + t;
    int d = (idx < N) ? g_deg[idx] : 0;
    int lane = t & 31, wp = t >> 5;
    int s = d;
    #pragma unroll
    for (int o = 1; o < 32; o <<= 1) {
        int u = __shfl_up_sync(0xffffffffu, s, o);
        if (lane >= o) s += u;
    }
    if (lane == 31) wsum[wp] = s;
    __syncthreads();
    if (wp == 0) {
        int w = wsum[lane];
        #pragma unroll
        for (int o = 1; o < 32; o <<= 1) {
            int u = __shfl_up_sync(0xffffffffu, w, o);
            if (lane >= o) w += u;
        }
        wsum[lane] = w;
    }
    __syncthreads();
    int incl = s + (wp > 0 ? wsum[wp - 1] : 0);
    if (t == SCANB - 1) base = atomicAdd(&g_total, incl);
    __syncthreads();
    if (idx < N) {
        int excl = base + incl - d;
        g_rowptr[idx] = excl;
        g_csr[excl]   = idx;          // self-loop edge first
        g_cursor[idx] = excl + 1;
    }
}

__global__ void k_scatter(const int* __restrict__ edges, int E) {
    int e = blockIdx.x * blockDim.x + threadIdx.x;
    if (e >= E) return;
    int s, d;
    if (g_is64) {
        s = (int)((const long long*)edges)[e];
        d = (int)((const long long*)edges)[(size_t)E + e];
    } else {
        s = edges[e];
        d = edges[E + e];
    }
    int p = atomicAdd(&g_cursor[d], 1);
    g_csr[p] = s;
}

// ---------------------------------------------------------------------------
// k_asad: x fp32 -> fp16 (g_xh) ; [64x64]@wext[64x16] -> a_src/a_dst ;
// fused per-head global max of a_src.
__global__ __launch_bounds__(256) void k_asad(const float* __restrict__ x, int N) {
    __shared__ __align__(16) __half xs[64 * 72];
    __shared__ __align__(16) __half ws[64 * 16];
    __shared__ __align__(16) float  fs[64 * 16];
    __shared__ unsigned gmx[8];

    int tid = threadIdx.x;
    int row0 = blockIdx.x * 64;

    for (int i = tid; i < 64 * 16; i += 256) {
        int r = i >> 4, c4 = (i & 15) * 4;
        float4 v = make_float4(0.f, 0.f, 0.f, 0.f);
        if (row0 + r < N) v = *(const float4*)&x[(size_t)(row0 + r) * 64 + c4];
        __half2 p0 = __floats2half2_rn(v.x, v.y);
        __half2 p1 = __floats2half2_rn(v.z, v.w);
        uint2 u = make_uint2(*(unsigned*)&p0, *(unsigned*)&p1);
        *(uint2*)&xs[r * 72 + c4] = u;
        if (row0 + r < N) *(uint2*)&g_xh[(size_t)(row0 + r) * 64 + c4] = u;
    }
    if (tid < 128) *(uint4*)&ws[tid * 8] = *(const uint4*)&g_wext[tid * 8];
    if (tid < 8) gmx[tid] = 0u;
    __syncthreads();

    int wp = tid >> 5;
    if (wp < 4) {
        wmma::fragment<wmma::accumulator, 16, 16, 16, float> c;
        wmma::fill_fragment(c, 0.f);
        #pragma unroll
        for (int k = 0; k < 4; k++) {
            wmma::fragment<wmma::matrix_a, 16, 16, 16, __half, wmma::row_major> a;
            wmma::fragment<wmma::matrix_b, 16, 16, 16, __half, wmma::row_major> b;
            wmma::load_matrix_sync(a, &xs[wp * 16 * 72 + k * 16], 72);
            wmma::load_matrix_sync(b, &ws[k * 16 * 16], 16);
            wmma::mma_sync(c, a, b, c);
        }
        wmma::store_matrix_sync(&fs[wp * 16 * 16], c, 16, wmma::mem_row_major);
    }
    __syncthreads();
    if (tid < 64) {
        int rowg = row0 + tid;
        if (rowg < N) {
            float4 s0 = *(const float4*)&fs[tid * 16 + 0];
            float4 s1 = *(const float4*)&fs[tid * 16 + 4];
            float4 d0 = *(const float4*)&fs[tid * 16 + 8];
            float4 d1 = *(const float4*)&fs[tid * 16 + 12];
            *(float4*)&g_as1[rowg * 8 + 0] = s0;
            *(float4*)&g_as1[rowg * 8 + 4] = s1;
            *(float4*)&g_ad1[rowg * 8 + 0] = d0;
            *(float4*)&g_ad1[rowg * 8 + 4] = d1;
            atomicMax(&gmx[0], f_enc(s0.x)); atomicMax(&gmx[1], f_enc(s0.y));
            atomicMax(&gmx[2], f_enc(s0.z)); atomicMax(&gmx[3], f_enc(s0.w));
            atomicMax(&gmx[4], f_enc(s1.x)); atomicMax(&gmx[5], f_enc(s1.y));
            atomicMax(&gmx[6], f_enc(s1.z)); atomicMax(&gmx[7], f_enc(s1.w));
        }
    }
    __syncthreads();
    if (tid < 8) atomicMax(&g_gms[tid], gmx[tid]);
}

// ---------------------------------------------------------------------------
// agg1: warp per node, TWO-PHASE (unchanged from round 13).
__global__ __launch_bounds__(256) void k_agg1(int N) {
    __shared__ __align__(16) float wsm[8][32][8];   // [warp][edge][head]
    __shared__ int   ssm[8][32];

    int tid = threadIdx.x;
    int lane = tid & 31, wp = tid >> 5;
    int node = blockIdx.x * 8 + wp;
    if (node >= N) return;

    int start = g_rowptr[node], deg = g_deg[node];

    float adv[8], mh[8], denA[8];
    {
        float4 lo = *(const float4*)&g_ad1[node * 8];
        float4 hi = *(const float4*)&g_ad1[node * 8 + 4];
        adv[0]=lo.x; adv[1]=lo.y; adv[2]=lo.z; adv[3]=lo.w;
        adv[4]=hi.x; adv[5]=hi.y; adv[6]=hi.z; adv[7]=hi.w;
    }
    #pragma unroll
    for (int h = 0; h < 8; h++) {
        float t = f_dec(g_gms[h]) + adv[h];
        mh[h] = (t >= 0.f) ? t : 0.2f * t;
        denA[h] = 0.f;
    }

    float accx[8], accy[8];
    #pragma unroll
    for (int h = 0; h < 8; h++) { accx[h] = 0.f; accy[h] = 0.f; }

    const __half2* xh2 = (const __half2*)g_xh;

    for (int base = 0; base < deg; base += 32) {
        int idx = base + lane;
        bool valid = idx < deg;
        int s = valid ? g_csr[start + idx] : 0;
        ssm[wp][lane] = s;
        float4 alo = *(const float4*)&g_as1[s * 8];
        float4 ahi = *(const float4*)&g_as1[s * 8 + 4];
        float as[8] = {alo.x, alo.y, alo.z, alo.w, ahi.x, ahi.y, ahi.z, ahi.w};
        #pragma unroll
        for (int h = 0; h < 8; h++) {
            float e = as[h] + adv[h];
            e = (e >= 0.f) ? e : 0.2f * e;
            float w = valid ? __expf(e - mh[h]) : 0.f;
            wsm[wp][lane][h] = w;
            denA[h] += w;
        }
        __syncwarp();
        int m = deg - base; if (m > 32) m = 32;
        #pragma unroll 4
        for (int j = 0; j < m; j++) {
            int s2 = ssm[wp][j];
            float4 wlo = *(const float4*)&wsm[wp][j][0];
            float4 whi = *(const float4*)&wsm[wp][j][4];
            float2 xv = __half22float2(xh2[s2 * 32 + lane]);
            accx[0] += wlo.x * xv.x; accy[0] += wlo.x * xv.y;
            accx[1] += wlo.y * xv.x; accy[1] += wlo.y * xv.y;
            accx[2] += wlo.z * xv.x; accy[2] += wlo.z * xv.y;
            accx[3] += wlo.w * xv.x; accy[3] += wlo.w * xv.y;
            accx[4] += whi.x * xv.x; accy[4] += whi.x * xv.y;
            accx[5] += whi.y * xv.x; accy[5] += whi.y * xv.y;
            accx[6] += whi.z * xv.x; accy[6] += whi.z * xv.y;
            accx[7] += whi.w * xv.x; accy[7] += whi.w * xv.y;
        }
        __syncwarp();
    }

    #pragma unroll
    for (int h = 0; h < 8; h++) {
        float d = denA[h];
        #pragma unroll
        for (int o = 16; o; o >>= 1) d += __shfl_xor_sync(0xffffffffu, d, o);
        float inv = __fdividef(1.f, d);
        __half2 hv = __floats2half2_rn(accx[h] * inv, accy[h] * inv);
        *(__half2*)&g_xa[(size_t)node * 512 + h * 64 + 2 * lane] = hv;
    }
}

// ---------------------------------------------------------------------------
// gemm2: fragments direct from GLOBAL (xa ldm 512, W1 ldm 512); per-warp smem
// result tile (syncwarp only); cross-warp h2v combine via smem atomics.
// Epilogue: +b1, ELU, *W2 -> h2v; fused h2v min/max.
__global__ __launch_bounds__(256) void k_gemm2(const float* __restrict__ b1,
                                               const float* __restrict__ W2, int N) {
    __shared__ __align__(16) __half wbuf[8][16 * 40];  // per-warp 16x32 tile, ldm 40
    __shared__ float hrow[64];

    int tid = threadIdx.x;
    int lane = tid & 31, wp = tid >> 5;
    int row0 = blockIdx.x * 64;
    int tm = wp >> 1, tn0 = wp & 1;   // rows tm*16.., cols tn0*32.. of each head

    if (tid < 64) hrow[tid] = 0.f;
    __syncthreads();

    int rl = lane >> 1;            // local row within warp tile (0..15)
    int ch = (lane & 1) * 16;      // channel offset within warp's 32 cols

    const __half* xaBase = &g_xa[(size_t)(row0 + tm * 16) * 512];
    float h2acc = 0.f;

    for (int head = 0; head < 8; head++) {
        int colH = head * 64 + tn0 * 32;     // this warp's 32-col slice
        wmma::fragment<wmma::accumulator, 16, 16, 16, float> c0, c1;
        wmma::fill_fragment(c0, 0.f);
        wmma::fill_fragment(c1, 0.f);
        #pragma unroll
        for (int k = 0; k < 4; k++) {
            wmma::fragment<wmma::matrix_a, 16, 16, 16, __half, wmma::row_major> a;
            wmma::fragment<wmma::matrix_b, 16, 16, 16, __half, wmma::row_major> b0, b1f;
            wmma::load_matrix_sync(a, xaBase + head * 64 + k * 16, 512);
            wmma::load_matrix_sync(b0,  &g_w1h[(size_t)(k * 16) * 512 + colH], 512);
            wmma::load_matrix_sync(b1f, &g_w1h[(size_t)(k * 16) * 512 + colH + 16], 512);
            wmma::mma_sync(c0, a, b0, c0);
            wmma::mma_sync(c1, a, b1f, c1);
        }
        wmma::fragment<wmma::accumulator, 16, 16, 16, __half> h0, h1f;
        #pragma unroll
        for (int i = 0; i < h0.num_elements; i++) {
            h0.x[i]  = __float2half_rn(c0.x[i]);
            h1f.x[i] = __float2half_rn(c1.x[i]);
        }
        wmma::store_matrix_sync(&wbuf[wp][0],  h0,  40, wmma::mem_row_major);
        wmma::store_matrix_sync(&wbuf[wp][16], h1f, 40, wmma::mem_row_major);
        __syncwarp();

        // epilogue: lane -> (row rl, 16 chans at colH+ch)
        uint4 u0 = *(const uint4*)&wbuf[wp][rl * 40 + ch];
        uint4 u1 = *(const uint4*)&wbuf[wp][rl * 40 + ch + 8];
        const __half2* q0 = (const __half2*)&u0;
        const __half2* q1 = (const __half2*)&u1;
        float y[16];
        #pragma unroll
        for (int k = 0; k < 4; k++) {
            float2 f0 = __half22float2(q0[k]);
            y[k * 2 + 0] = f0.x; y[k * 2 + 1] = f0.y;
            float2 f1 = __half22float2(q1[k]);
            y[8 + k * 2 + 0] = f1.x; y[8 + k * 2 + 1] = f1.y;
        }
        #pragma unroll
        for (int j = 0; j < 4; j++) {
            float4 bb = *(const float4*)&b1[colH + ch + j * 4];
            float4 w2 = *(const float4*)&W2[colH + ch + j * 4];
            float o0 = y[j*4+0] + bb.x;
            float o1 = y[j*4+1] + bb.y;
            float o2 = y[j*4+2] + bb.z;
            float o3 = y[j*4+3] + bb.w;
            o0 = (o0 > 0.f) ? o0 : expm1f(o0);
            o1 = (o1 > 0.f) ? o1 : expm1f(o1);
            o2 = (o2 > 0.f) ? o2 : expm1f(o2);
            o3 = (o3 > 0.f) ? o3 : expm1f(o3);
            h2acc += o0 * w2.x + o1 * w2.y + o2 * w2.z + o3 * w2.w;
        }
        __syncwarp();   // wbuf reused next head
    }

    // pair-reduce (lanes l, l^1 share row rl), combine across warps via smem
    h2acc += __shfl_xor_sync(0xffffffffu, h2acc, 1);
    if ((lane & 1) == 0) atomicAdd(&hrow[tm * 16 + rl], h2acc);
    __syncthreads();

    if (tid < 64) {
        int rowg = row0 + tid;
        bool valid = rowg < N;
        float v = hrow[tid];
        if (valid) g_h2v[rowg] = v;
        float mxv = valid ? v : -FLT_MAX;
        float mnv = valid ? v :  FLT_MAX;
        #pragma unroll
        for (int o = 16; o; o >>= 1) {
            mxv = fmaxf(mxv, __shfl_xor_sync(0xffffffffu, mxv, o));
            mnv = fminf(mnv, __shfl_xor_sync(0xffffffffu, mnv, o));
        }
        if ((tid & 31) == 0) {
            atomicMax(&g_g2[0], f_enc(mxv));
            atomicMax(&g_g2[1], f_enc(-mnv));
        }
    }
}

// ---------------------------------------------------------------------------
__global__ __launch_bounds__(256) void k_agg2(const float* __restrict__ sa2p,
                                              const float* __restrict__ sd2p,
                                              const float* __restrict__ b2p,
                                              float* __restrict__ out, int N) {
    int g = blockIdx.x * 256 + threadIdx.x;
    int node = g >> 5, lane = g & 31;
    if (node >= N) return;
    float sa = sa2p[0], sd = sd2p[0];
    float gmax = f_dec(g_g2[0]);
    float gmin = -f_dec(g_g2[1]);
    int start = g_rowptr[node];
    int end = start + g_deg[node];
    float adv = g_h2v[node] * sd;

    float pre = (sa >= 0.f ? sa * gmax : sa * gmin) + adv;
    float lm = (pre >= 0.f) ? pre : 0.2f * pre;

    float den = 0.f, num = 0.f;
    for (int i = start + lane; i < end; i += 32) {
        float hv = g_h2v[g_csr[i]];
        float e = hv * sa + adv;
        e = (e >= 0.f) ? e : 0.2f * e;
        float w = __expf(e - lm);
        den += w;
        num += w * hv;
    }
    #pragma unroll
    for (int o = 16; o; o >>= 1) {
        den += __shfl_xor_sync(0xffffffffu, den, o);
        num += __shfl_xor_sync(0xffffffffu, num, o);
    }
    if (lane == 0) out[node] = num / den + b2p[0];
}

// ---------------------------------------------------------------------------
extern "C" void kernel_launch(void* const* d_in, const int* in_sizes, int n_in,
                              void* d_out, int out_size) {
    const float* x      = (const float*)d_in[0];
    const int*   edges  = (const int*)d_in[1];
    const float* W1     = (const float*)d_in[2];
    const float* att_s1 = (const float*)d_in[3];
    const float* att_d1 = (const float*)d_in[4];
    const float* b1     = (const float*)d_in[5];
    const float* W2     = (const float*)d_in[6];
    const float* att_s2 = (const float*)d_in[7];
    const float* att_d2 = (const float*)d_in[8];
    const float* b2     = (const float*)d_in[9];
    float* out = (float*)d_out;

    int N = in_sizes[0] / 64;
    int E = in_sizes[1] / 2;
    int nb = (N + SCANB - 1) / SCANB;

    k_pre<<<200, 256>>>(W1, att_s1, att_d1, (const unsigned int*)edges, E, N); // 0
    k_deg<<<(E + 255) / 256, 256>>>(edges, E);                        // 1
    k_build<<<nb, SCANB>>>(N);                                        // 2
    k_scatter<<<(E + 255) / 256, 256>>>(edges, E);                    // 3 <- profiled
    k_asad<<<(N + 63) / 64, 256>>>(x, N);                             // 4
    k_agg1<<<(N + 7) / 8, 256>>>(N);                                  // 5
    k_gemm2<<<(N + 63) / 64, 256>>>(b1, W2, N);                       // 6
    k_agg2<<<(N * 32 + 255) / 256, 256>>>(att_s2, att_d2, b2, out, N); // 7
}

// round 15
// speedup vs baseline: 1.2688x; 1.2688x over previous
#include <cuda_runtime.h>
#include <cuda_fp16.h>
#include <mma.h>
#include <math.h>
#include <float.h>

using namespace nvcuda;

// ---------------------------------------------------------------------------
// GAT 2-layer.  Softmax-aggregate raw x (pre-GEMM), apply W1 after as dense
// tensor-core GEMM (fp16 smem staging — global-fragment variant was 2x worse);
// h1 never materialized.  CSR build forked onto a side stream, overlapped
// with x conversion + attention-coefficient GEMM.
// ---------------------------------------------------------------------------

#define MAXN 50048
#define MAXE 800000
#define MAXT (MAXE + MAXN)
#define SCANB 1024

__device__ __half g_xh[(size_t)MAXN * 64];    // x in fp16 (gather source)
__device__ __half g_xa[(size_t)MAXN * 512];   // normalized aggregated x, per head
__device__ __half g_w1h[64 * 512];            // W1 fp16
__device__ __half g_wext[64 * 16];            // W1 @ att (a_src 0-7, a_dst 8-15)
__device__ float g_as1[MAXN * 8];
__device__ float g_ad1[MAXN * 8];
__device__ int   g_deg[MAXN];
__device__ int   g_rowptr[MAXN];
__device__ int   g_cursor[MAXN];
__device__ int   g_csr[MAXT];
__device__ float g_h2v[MAXN];
__device__ unsigned g_gms[8];
__device__ unsigned g_g2[2];
__device__ int   g_total;
__device__ int   g_is64;

__device__ __forceinline__ unsigned f_enc(float f) {
    unsigned u = __float_as_uint(f);
    return (u & 0x80000000u) ? ~u : (u | 0x80000000u);
}
__device__ __forceinline__ float f_dec(unsigned e) {
    return __uint_as_float((e & 0x80000000u) ? (e & 0x7fffffffu) : ~e);
}

// ---------------------------------------------------------------------------
__global__ void k_pre(const float* __restrict__ W,
                      const float* __restrict__ att_s,
                      const float* __restrict__ att_d,
                      const unsigned int* __restrict__ edges, int E, int N) {
    int g = blockIdx.x * blockDim.x + threadIdx.x;
    int stride = gridDim.x * blockDim.x;
    for (int i = g; i < N; i += stride) g_deg[i] = 1;   // self-loop
    for (int i = g * 4; i < 64 * 512; i += stride * 4) {
        float4 v = *(const float4*)&W[i];
        __half2 p0 = __floats2half2_rn(v.x, v.y);
        __half2 p1 = __floats2half2_rn(v.z, v.w);
        *(uint2*)&g_w1h[i] = make_uint2(*(unsigned*)&p0, *(unsigned*)&p1);
    }
    for (int idx = g; idx < 64 * 16; idx += stride) {
        int k = idx >> 4, j = idx & 15;
        int head = j & 7;
        const float* att = (j < 8) ? att_s : att_d;
        float s = 0.f;
        const float* wr = &W[(size_t)k * 512 + head * 64];
        const float* ar = &att[head * 64];
        #pragma unroll 8
        for (int c = 0; c < 64; c++) s += wr[c] * ar[c];
        g_wext[k * 16 + j] = __float2half_rn(s);
    }
    if (g < 8) g_gms[g] = 0u;
    if (g < 2) g_g2[g] = 0u;
    if (g == 0) {
        g_total = 0;
        int n = E < 64 ? E : 64;
        int all0 = 1;
        for (int j = 0; j < n; j++)
            if (edges[2 * j + 1] != 0u) all0 = 0;
        g_is64 = all0;
    }
}

__global__ void k_deg(const int* __restrict__ edges, int E) {
    int e = blockIdx.x * blockDim.x + threadIdx.x;
    if (e >= E) return;
    int d = g_is64 ? (int)((const long long*)edges)[(size_t)E + e]
                   : edges[E + e];
    atomicAdd(&g_deg[d], 1);
}

// Single-kernel CSR build: block-local scan + atomic base allocation.
__global__ __launch_bounds__(SCANB) void k_build(int N) {
    __shared__ int wsum[32];
    __shared__ int base;
    int t = threadIdx.x, idx = blockIdx.x * SCANB + t;
    int d = (idx < N) ? g_deg[idx] : 0;
    int lane = t & 31, wp = t >> 5;
    int s = d;
    #pragma unroll
    for (int o = 1; o < 32; o <<= 1) {
        int u = __shfl_up_sync(0xffffffffu, s, o);
        if (lane >= o) s += u;
    }
    if (lane == 31) wsum[wp] = s;
    __syncthreads();
    if (wp == 0) {
        int w = wsum[lane];
        #pragma unroll
        for (int o = 1; o < 32; o <<= 1) {
            int u = __shfl_up_sync(0xffffffffu, w, o);
            if (lane >= o) w += u;
        }
        wsum[lane] = w;
    }
    __syncthreads();
    int incl = s + (wp > 0 ? wsum[wp - 1] : 0);
    if (t == SCANB - 1) base = atomicAdd(&g_total, incl);
    __syncthreads();
    if (idx < N) {
        int excl = base + incl - d;
        g_rowptr[idx] = excl;
        g_csr[excl]   = idx;          // self-loop edge first
        g_cursor[idx] = excl + 1;
    }
}

__global__ void k_scatter(const int* __restrict__ edges, int E) {
    int e = blockIdx.x * blockDim.x + threadIdx.x;
    if (e >= E) return;
    int s, d;
    if (g_is64) {
        s = (int)((const long long*)edges)[e];
        d = (int)((const long long*)edges)[(size_t)E + e];
    } else {
        s = edges[e];
        d = edges[E + e];
    }
    int p = atomicAdd(&g_cursor[d], 1);
    g_csr[p] = s;
}

// ---------------------------------------------------------------------------
// k_asad: x fp32 -> fp16 (g_xh) ; [64x64]@wext[64x16] -> a_src/a_dst ;
// fused per-head global max of a_src.
__global__ __launch_bounds__(256) void k_asad(const float* __restrict__ x, int N) {
    __shared__ __align__(16) __half xs[64 * 72];
    __shared__ __align__(16) __half ws[64 * 16];
    __shared__ __align__(16) float  fs[64 * 16];
    __shared__ unsigned gmx[8];

    int tid = threadIdx.x;
    int row0 = blockIdx.x * 64;

    for (int i = tid; i < 64 * 16; i += 256) {
        int r = i >> 4, c4 = (i & 15) * 4;
        float4 v = make_float4(0.f, 0.f, 0.f, 0.f);
        if (row0 + r < N) v = *(const float4*)&x[(size_t)(row0 + r) * 64 + c4];
        __half2 p0 = __floats2half2_rn(v.x, v.y);
        __half2 p1 = __floats2half2_rn(v.z, v.w);
        uint2 u = make_uint2(*(unsigned*)&p0, *(unsigned*)&p1);
        *(uint2*)&xs[r * 72 + c4] = u;
        if (row0 + r < N) *(uint2*)&g_xh[(size_t)(row0 + r) * 64 + c4] = u;
    }
    if (tid < 128) *(uint4*)&ws[tid * 8] = *(const uint4*)&g_wext[tid * 8];
    if (tid < 8) gmx[tid] = 0u;
    __syncthreads();

    int wp = tid >> 5;
    if (wp < 4) {
        wmma::fragment<wmma::accumulator, 16, 16, 16, float> c;
        wmma::fill_fragment(c, 0.f);
        #pragma unroll
        for (int k = 0; k < 4; k++) {
            wmma::fragment<wmma::matrix_a, 16, 16, 16, __half, wmma::row_major> a;
            wmma::fragment<wmma::matrix_b, 16, 16, 16, __half, wmma::row_major> b;
            wmma::load_matrix_sync(a, &xs[wp * 16 * 72 + k * 16], 72);
            wmma::load_matrix_sync(b, &ws[k * 16 * 16], 16);
            wmma::mma_sync(c, a, b, c);
        }
        wmma::store_matrix_sync(&fs[wp * 16 * 16], c, 16, wmma::mem_row_major);
    }
    __syncthreads();
    if (tid < 64) {
        int rowg = row0 + tid;
        if (rowg < N) {
            float4 s0 = *(const float4*)&fs[tid * 16 + 0];
            float4 s1 = *(const float4*)&fs[tid * 16 + 4];
            float4 d0 = *(const float4*)&fs[tid * 16 + 8];
            float4 d1 = *(const float4*)&fs[tid * 16 + 12];
            *(float4*)&g_as1[rowg * 8 + 0] = s0;
            *(float4*)&g_as1[rowg * 8 + 4] = s1;
            *(float4*)&g_ad1[rowg * 8 + 0] = d0;
            *(float4*)&g_ad1[rowg * 8 + 4] = d1;
            atomicMax(&gmx[0], f_enc(s0.x)); atomicMax(&gmx[1], f_enc(s0.y));
            atomicMax(&gmx[2], f_enc(s0.z)); atomicMax(&gmx[3], f_enc(s0.w));
            atomicMax(&gmx[4], f_enc(s1.x)); atomicMax(&gmx[5], f_enc(s1.y));
            atomicMax(&gmx[6], f_enc(s1.z)); atomicMax(&gmx[7], f_enc(s1.w));
        }
    }
    __syncthreads();
    if (tid < 8) atomicMax(&g_gms[tid], gmx[tid]);
}

// ---------------------------------------------------------------------------
// agg1: warp per node, TWO-PHASE (round-13 proven version).
__global__ __launch_bounds__(256) void k_agg1(int N) {
    __shared__ __align__(16) float wsm[8][32][8];   // [warp][edge][head]
    __shared__ int   ssm[8][32];

    int tid = threadIdx.x;
    int lane = tid & 31, wp = tid >> 5;
    int node = blockIdx.x * 8 + wp;
    if (node >= N) return;

    int start = g_rowptr[node], deg = g_deg[node];

    float adv[8], mh[8], denA[8];
    {
        float4 lo = *(const float4*)&g_ad1[node * 8];
        float4 hi = *(const float4*)&g_ad1[node * 8 + 4];
        adv[0]=lo.x; adv[1]=lo.y; adv[2]=lo.z; adv[3]=lo.w;
        adv[4]=hi.x; adv[5]=hi.y; adv[6]=hi.z; adv[7]=hi.w;
    }
    #pragma unroll
    for (int h = 0; h < 8; h++) {
        float t = f_dec(g_gms[h]) + adv[h];
        mh[h] = (t >= 0.f) ? t : 0.2f * t;
        denA[h] = 0.f;
    }

    float accx[8], accy[8];
    #pragma unroll
    for (int h = 0; h < 8; h++) { accx[h] = 0.f; accy[h] = 0.f; }

    const __half2* xh2 = (const __half2*)g_xh;

    for (int base = 0; base < deg; base += 32) {
        int idx = base + lane;
        bool valid = idx < deg;
        int s = valid ? g_csr[start + idx] : 0;
        ssm[wp][lane] = s;
        float4 alo = *(const float4*)&g_as1[s * 8];
        float4 ahi = *(const float4*)&g_as1[s * 8 + 4];
        float as[8] = {alo.x, alo.y, alo.z, alo.w, ahi.x, ahi.y, ahi.z, ahi.w};
        #pragma unroll
        for (int h = 0; h < 8; h++) {
            float e = as[h] + adv[h];
            e = (e >= 0.f) ? e : 0.2f * e;
            float w = valid ? __expf(e - mh[h]) : 0.f;
            wsm[wp][lane][h] = w;
            denA[h] += w;
        }
        __syncwarp();
        int m = deg - base; if (m > 32) m = 32;
        #pragma unroll 4
        for (int j = 0; j < m; j++) {
            int s2 = ssm[wp][j];
            float4 wlo = *(const float4*)&wsm[wp][j][0];
            float4 whi = *(const float4*)&wsm[wp][j][4];
            float2 xv = __half22float2(xh2[s2 * 32 + lane]);
            accx[0] += wlo.x * xv.x; accy[0] += wlo.x * xv.y;
            accx[1] += wlo.y * xv.x; accy[1] += wlo.y * xv.y;
            accx[2] += wlo.z * xv.x; accy[2] += wlo.z * xv.y;
            accx[3] += wlo.w * xv.x; accy[3] += wlo.w * xv.y;
            accx[4] += whi.x * xv.x; accy[4] += whi.x * xv.y;
            accx[5] += whi.y * xv.x; accy[5] += whi.y * xv.y;
            accx[6] += whi.z * xv.x; accy[6] += whi.z * xv.y;
            accx[7] += whi.w * xv.x; accy[7] += whi.w * xv.y;
        }
        __syncwarp();
    }

    #pragma unroll
    for (int h = 0; h < 8; h++) {
        float d = denA[h];
        #pragma unroll
        for (int o = 16; o; o >>= 1) d += __shfl_xor_sync(0xffffffffu, d, o);
        float inv = __fdividef(1.f, d);
        __half2 hv = __floats2half2_rn(accx[h] * inv, accy[h] * inv);
        *(__half2*)&g_xa[(size_t)node * 512 + h * 64 + 2 * lane] = hv;
    }
}

// ---------------------------------------------------------------------------
// gemm2 (round-13 proven version): fp16 smem staging, LDSM-friendly; epilogue
// +b1, ELU, *W2 -> h2v (xa pre-normalized).  Fused h2v min/max.
__global__ __launch_bounds__(256) void k_gemm2(const float* __restrict__ b1,
                                               const float* __restrict__ W2, int N) {
    __shared__ __align__(16) __half as_[64 * 72];
    __shared__ __align__(16) __half bs[64 * 72];
    __shared__ __align__(16) __half fsh[64 * 72];

    int tid = threadIdx.x;
    int row0 = blockIdx.x * 64;
    int wp = tid >> 5;
    int tm = wp >> 1;
    int tn0 = (wp & 1) * 2;
    int r = tid >> 2, sub = tid & 3;
    int rowg = row0 + r;

    float h2acc = 0.f;

    for (int head = 0; head < 8; head++) {
        int col0 = head * 64;
        for (int i = tid; i < 64 * 8; i += 256) {
            int rr = i >> 3, c8 = (i & 7) * 8;
            *(uint4*)&as_[rr * 72 + c8] = *(const uint4*)&g_xa[(size_t)(row0 + rr) * 512 + col0 + c8];
            *(uint4*)&bs[rr * 72 + c8]  = *(const uint4*)&g_w1h[(size_t)rr * 512 + col0 + c8];
        }
        __syncthreads();

        wmma::fragment<wmma::accumulator, 16, 16, 16, float> c0, c1;
        wmma::fill_fragment(c0, 0.f);
        wmma::fill_fragment(c1, 0.f);
        #pragma unroll
        for (int k = 0; k < 4; k++) {
            wmma::fragment<wmma::matrix_a, 16, 16, 16, __half, wmma::row_major> a;
            wmma::fragment<wmma::matrix_b, 16, 16, 16, __half, wmma::row_major> b0, b1f;
            wmma::load_matrix_sync(a, &as_[tm * 16 * 72 + k * 16], 72);
            wmma::load_matrix_sync(b0, &bs[k * 16 * 72 + tn0 * 16], 72);
            wmma::load_matrix_sync(b1f, &bs[k * 16 * 72 + (tn0 + 1) * 16], 72);
            wmma::mma_sync(c0, a, b0, c0);
            wmma::mma_sync(c1, a, b1f, c1);
        }
        wmma::fragment<wmma::accumulator, 16, 16, 16, __half> h0, h1f;
        #pragma unroll
        for (int i = 0; i < h0.num_elements; i++) {
            h0.x[i]  = __float2half_rn(c0.x[i]);
            h1f.x[i] = __float2half_rn(c1.x[i]);
        }
        wmma::store_matrix_sync(&fsh[tm * 16 * 72 + tn0 * 16], h0, 72, wmma::mem_row_major);
        wmma::store_matrix_sync(&fsh[tm * 16 * 72 + (tn0 + 1) * 16], h1f, 72, wmma::mem_row_major);
        __syncthreads();

        uint4 u0 = *(const uint4*)&fsh[r * 72 + sub * 16];
        uint4 u1 = *(const uint4*)&fsh[r * 72 + sub * 16 + 8];
        const __half2* q0 = (const __half2*)&u0;
        const __half2* q1 = (const __half2*)&u1;
        float y[16];
        #pragma unroll
        for (int k = 0; k < 4; k++) {
            float2 f0 = __half22float2(q0[k]);
            y[k * 2 + 0] = f0.x; y[k * 2 + 1] = f0.y;
            float2 f1 = __half22float2(q1[k]);
            y[8 + k * 2 + 0] = f1.x; y[8 + k * 2 + 1] = f1.y;
        }
        #pragma unroll
        for (int j = 0; j < 4; j++) {
            float4 bb = *(const float4*)&b1[col0 + sub * 16 + j * 4];
            float4 w2 = *(const float4*)&W2[col0 + sub * 16 + j * 4];
            float o0 = y[j*4+0] + bb.x;
            float o1 = y[j*4+1] + bb.y;
            float o2 = y[j*4+2] + bb.z;
            float o3 = y[j*4+3] + bb.w;
            o0 = (o0 > 0.f) ? o0 : expm1f(o0);
            o1 = (o1 > 0.f) ? o1 : expm1f(o1);
            o2 = (o2 > 0.f) ? o2 : expm1f(o2);
            o3 = (o3 > 0.f) ? o3 : expm1f(o3);
            h2acc += o0 * w2.x + o1 * w2.y + o2 * w2.z + o3 * w2.w;
        }
        __syncthreads();   // fsh reused next head
    }

    h2acc += __shfl_xor_sync(0xffffffffu, h2acc, 1);
    h2acc += __shfl_xor_sync(0xffffffffu, h2acc, 2);
    bool valid = (sub == 0 && rowg < N);
    if (valid) g_h2v[rowg] = h2acc;

    float mxv = valid ? h2acc : -FLT_MAX;
    float mnv = valid ? h2acc :  FLT_MAX;
    #pragma unroll
    for (int o = 16; o; o >>= 1) {
        mxv = fmaxf(mxv, __shfl_xor_sync(0xffffffffu, mxv, o));
        mnv = fminf(mnv, __shfl_xor_sync(0xffffffffu, mnv, o));
    }
    if ((tid & 31) == 0) {
        atomicMax(&g_g2[0], f_enc(mxv));
        atomicMax(&g_g2[1], f_enc(-mnv));
    }
}

// ---------------------------------------------------------------------------
__global__ __launch_bounds__(256) void k_agg2(const float* __restrict__ sa2p,
                                              const float* __restrict__ sd2p,
                                              const float* __restrict__ b2p,
                                              float* __restrict__ out, int N) {
    int g = blockIdx.x * 256 + threadIdx.x;
    int node = g >> 5, lane = g & 31;
    if (node >= N) return;
    float sa = sa2p[0], sd = sd2p[0];
    float gmax = f_dec(g_g2[0]);
    float gmin = -f_dec(g_g2[1]);
    int start = g_rowptr[node];
    int end = start + g_deg[node];
    float adv = g_h2v[node] * sd;

    float pre = (sa >= 0.f ? sa * gmax : sa * gmin) + adv;
    float lm = (pre >= 0.f) ? pre : 0.2f * pre;

    float den = 0.f, num = 0.f;
    for (int i = start + lane; i < end; i += 32) {
        float hv = g_h2v[g_csr[i]];
        float e = hv * sa + adv;
        e = (e >= 0.f) ? e : 0.2f * e;
        float w = __expf(e - lm);
        den += w;
        num += w * hv;
    }
    #pragma unroll
    for (int o = 16; o; o >>= 1) {
        den += __shfl_xor_sync(0xffffffffu, den, o);
        num += __shfl_xor_sync(0xffffffffu, num, o);
    }
    if (lane == 0) out[node] = num / den + b2p[0];
}

// ---------------------------------------------------------------------------
extern "C" void kernel_launch(void* const* d_in, const int* in_sizes, int n_in,
                              void* d_out, int out_size) {
    const float* x      = (const float*)d_in[0];
    const int*   edges  = (const int*)d_in[1];
    const float* W1     = (const float*)d_in[2];
    const float* att_s1 = (const float*)d_in[3];
    const float* att_d1 = (const float*)d_in[4];
    const float* b1     = (const float*)d_in[5];
    const float* W2     = (const float*)d_in[6];
    const float* att_s2 = (const float*)d_in[7];
    const float* att_d2 = (const float*)d_in[8];
    const float* b2     = (const float*)d_in[9];
    float* out = (float*)d_out;

    int N = in_sizes[0] / 64;
    int E = in_sizes[1] / 2;
    int nb = (N + SCANB - 1) / SCANB;

    // Side stream + events, created once (first call is the uncaptured
    // correctness run). Fork/join with events is graph-capturable.
    static cudaStream_t s1 = nullptr;
    static cudaEvent_t evFork = nullptr, evJoin = nullptr;
    if (!s1) {
        cudaStreamCreateWithFlags(&s1, cudaStreamNonBlocking);
        cudaEventCreateWithFlags(&evFork, cudaEventDisableTiming);
        cudaEventCreateWithFlags(&evJoin, cudaEventDisableTiming);
    }

    k_pre<<<200, 256>>>(W1, att_s1, att_d1, (const unsigned int*)edges, E, N);
    cudaEventRecord(evFork, 0);
    cudaStreamWaitEvent(s1, evFork, 0);

    // side stream: CSR build chain
    k_deg<<<(E + 255) / 256, 256, 0, s1>>>(edges, E);
    k_build<<<nb, SCANB, 0, s1>>>(N);
    k_scatter<<<(E + 255) / 256, 256, 0, s1>>>(edges, E);
    cudaEventRecord(evJoin, s1);

    // main stream: x conversion + attention coefficients (independent)
    k_asad<<<(N + 63) / 64, 256>>>(x, N);

    cudaStreamWaitEvent(0, evJoin, 0);
    k_agg1<<<(N + 7) / 8, 256>>>(N);
    k_gemm2<<<(N + 63) / 64, 256>>>(b1, W2, N);
    k_agg2<<<(N * 32 + 255) / 256, 256>>>(att_s2, att_d2, b2, out, N);
}